// round 15
// baseline (speedup 1.0000x reference)
#include <cuda_runtime.h>
#include <math.h>

// Problem constants
#define BB 2
#define SS 2048
#define DD 1024
#define NH 16
#define NKV 4
#define DH 64
#define MM (BB*SS)   // 4096

// Permuted-row layout (4 groups of 16 floats at offsets 0,16,36,52; row stride 72)
#define PR 72
#define VTROW (32 * PR)

#define LOG2E 1.44269504088896340736f

// ---------------- scratch (16B aligned for cp.async) ----------------
__device__ __align__(16) float g_q  [MM * DD];
__device__ __align__(16) float g_k  [MM * NKV*DH];
__device__ __align__(16) float g_v  [MM * NKV*DH];
__device__ __align__(16) float g_qr [MM * DD];
__device__ __align__(16) float g_kr [BB*NKV*SS * PR];
__device__ __align__(16) float g_vt [BB*NKV*DH * VTROW];
__device__ __align__(16) float g_ao [MM * DD];
__device__ __align__(16) float g_mb [MM];
// tf32-pre-rounded copies of inputs
__device__ __align__(16) float g_hsr[MM * DD];
__device__ __align__(16) float g_wq [DD * DD];
__device__ __align__(16) float g_wk [DD * NKV*DH];
__device__ __align__(16) float g_wv [DD * NKV*DH];
__device__ __align__(16) float g_wo [DD * DD];

// ---------------- helpers ----------------
__device__ __forceinline__ float f2tf(float x) {
    unsigned u;
    asm("cvt.rna.tf32.f32 %0, %1;" : "=r"(u) : "f"(x));
    return __uint_as_float(u);
}

__device__ __forceinline__ float ex2(float x) {
    float y;
    asm("ex2.approx.f32 %0, %1;" : "=f"(y) : "f"(x));
    return y;
}

__device__ __forceinline__ void mma8(float* d, const unsigned* a, const unsigned* b,
                                     const float* c) {
    asm volatile(
        "mma.sync.aligned.m16n8k8.row.col.f32.tf32.tf32.f32 "
        "{%0,%1,%2,%3}, {%4,%5,%6,%7}, {%8,%9}, {%10,%11,%12,%13};"
        : "=f"(d[0]), "=f"(d[1]), "=f"(d[2]), "=f"(d[3])
        : "r"(a[0]), "r"(a[1]), "r"(a[2]), "r"(a[3]),
          "r"(b[0]), "r"(b[1]),
          "f"(c[0]), "f"(c[1]), "f"(c[2]), "f"(c[3]));
}

__device__ __forceinline__ unsigned sm_u32(const void* p) {
    unsigned a;
    asm("{ .reg .u64 t; cvta.to.shared.u64 t, %1; cvt.u32.u64 %0, t; }"
        : "=r"(a) : "l"(p));
    return a;
}
#define CPA16(d, s) asm volatile("cp.async.cg.shared.global [%0], [%1], 16;" :: "r"(d), "l"(s))
#define CPC()  asm volatile("cp.async.commit_group;")
#define CPW0() asm volatile("cp.async.wait_group 0;" ::: "memory")

// ---------------- prep: tf32-round inputs once ----------------
__global__ void prep_kernel(const float4* __restrict__ hs, const float4* __restrict__ Wq,
                            const float4* __restrict__ Wk, const float4* __restrict__ Wv,
                            const float4* __restrict__ Wo,
                            float4* __restrict__ hsr, float4* __restrict__ wq,
                            float4* __restrict__ wk,  float4* __restrict__ wv,
                            float4* __restrict__ wo)
{
    long i = (long)blockIdx.x * 256 + threadIdx.x;
    const float4* src; float4* dst;
    if (i < 1048576)            { src = hs; dst = hsr; }
    else if (i < 1310720)       { i -= 1048576; src = Wq; dst = wq; }
    else if (i < 1376256)       { i -= 1310720; src = Wk; dst = wk; }
    else if (i < 1441792)       { i -= 1376256; src = Wv; dst = wv; }
    else if (i < 1703936)       { i -= 1441792; src = Wo; dst = wo; }
    else return;
    float4 v = src[i];
    v.x = f2tf(v.x); v.y = f2tf(v.y); v.z = f2tf(v.z); v.w = f2tf(v.w);
    dst[i] = v;
}

// ---------------- tf32 GEMM body: cp.async ping-pong, pure-copy tiles ----------
#define TBM 128
#define TBN 128
#define TBK 32
#define ASTR 36
#define BSTR 136
#define GSMEM ((2 * TBM * ASTR + 2 * TBK * BSTR) * 4)   // 70 KB

__device__ __forceinline__ void gemm_body(
    const float* __restrict__ A, const float* __restrict__ B,
    const float* __restrict__ bias, float* __restrict__ C,
    int N, int K, int bm, int bn, bool cvtOut, float* sm)
{
    float* As = sm;
    float* Bs = sm + 2 * TBM * ASTR;

    const int tid  = threadIdx.x;
    const int lane = tid & 31;
    const int warp = tid >> 5;
    const int gr   = lane >> 2;
    const int tig  = lane & 3;
    const int warp_m = (warp & 1) * 64;
    const int warp_n = (warp >> 1) * 32;

    float acc[4][4][4];
#pragma unroll
    for (int mt = 0; mt < 4; mt++)
#pragma unroll
        for (int nt = 0; nt < 4; nt++)
#pragma unroll
            for (int i = 0; i < 4; i++) acc[mt][nt][i] = 0.f;

    auto issue = [&](int t) {
        int k0 = t * TBK;
        int bi = t & 1;
        float* Asb = As + bi * TBM * ASTR;
        float* Bsb = Bs + bi * TBK * BSTR;
#pragma unroll
        for (int i = 0; i < 4; i++) {
            int idx = tid + i * 256;
            int am = idx >> 3, ac = (idx & 7) << 2;
            CPA16(sm_u32(&Asb[am * ASTR + ac]), A + (size_t)(bm + am) * K + k0 + ac);
            int bk = idx >> 5, bnn = (idx & 31) << 2;
            CPA16(sm_u32(&Bsb[bk * BSTR + bnn]), B + (size_t)(k0 + bk) * N + bn + bnn);
        }
        CPC();
    };

    const int T = K / TBK;
    issue(0);

    for (int t = 0; t < T; t++) {
        CPW0();
        __syncthreads();
        if (t + 1 < T) issue(t + 1);

        const float* Asb = As + (t & 1) * TBM * ASTR;
        const float* Bsb = Bs + (t & 1) * TBK * BSTR;
#pragma unroll
        for (int ks = 0; ks < 4; ks++) {
            int kk = ks * 8;
            unsigned afr[4][4], bfr[4][2];
#pragma unroll
            for (int mt = 0; mt < 4; mt++) {
                int r0 = warp_m + mt * 16 + gr;
                afr[mt][0] = __float_as_uint(Asb[r0 * ASTR + kk + tig]);
                afr[mt][1] = __float_as_uint(Asb[(r0 + 8) * ASTR + kk + tig]);
                afr[mt][2] = __float_as_uint(Asb[r0 * ASTR + kk + tig + 4]);
                afr[mt][3] = __float_as_uint(Asb[(r0 + 8) * ASTR + kk + tig + 4]);
            }
#pragma unroll
            for (int nt = 0; nt < 4; nt++) {
                int c0 = warp_n + nt * 8 + gr;
                bfr[nt][0] = __float_as_uint(Bsb[(kk + tig) * BSTR + c0]);
                bfr[nt][1] = __float_as_uint(Bsb[(kk + tig + 4) * BSTR + c0]);
            }
#pragma unroll
            for (int mt = 0; mt < 4; mt++)
#pragma unroll
                for (int nt = 0; nt < 4; nt++)
                    mma8(acc[mt][nt], afr[mt], bfr[nt], acc[mt][nt]);
        }
    }

#pragma unroll
    for (int mt = 0; mt < 4; mt++) {
        int r0 = bm + warp_m + mt * 16 + gr;
#pragma unroll
        for (int nt = 0; nt < 4; nt++) {
            int c0 = bn + warp_n + nt * 8 + 2 * tig;
            float bx = bias[c0], by = bias[c0 + 1];
            float2 o0 = make_float2(acc[mt][nt][0] + bx, acc[mt][nt][1] + by);
            float2 o1 = make_float2(acc[mt][nt][2] + bx, acc[mt][nt][3] + by);
            if (cvtOut) {
                o0.x = f2tf(o0.x); o0.y = f2tf(o0.y);
                o1.x = f2tf(o1.x); o1.y = f2tf(o1.y);
            }
            *(float2*)(&C[(size_t)r0 * N + c0]) = o0;
            *(float2*)(&C[(size_t)(r0 + 8) * N + c0]) = o1;
        }
    }
}

// ---- merged Q/K/V projections: grid (12, 32) ----
__global__ __launch_bounds__(256)
void proj_all(const float* __restrict__ hs,
              const float* __restrict__ Wq, const float* __restrict__ bq,
              const float* __restrict__ Wk, const float* __restrict__ bk,
              const float* __restrict__ Wv, const float* __restrict__ bv,
              float* __restrict__ q, float* __restrict__ k, float* __restrict__ v)
{
    extern __shared__ float sm[];
    int bx = blockIdx.x;
    const float *B, *bias; float* C; int N, bn; bool cvt;
    if (bx < 8)       { B = Wq; bias = bq; C = q; N = DD;       bn = bx * TBN;        cvt = false; }
    else if (bx < 10) { B = Wk; bias = bk; C = k; N = NKV * DH; bn = (bx - 8) * TBN;  cvt = false; }
    else              { B = Wv; bias = bv; C = v; N = NKV * DH; bn = (bx - 10) * TBN; cvt = true;  }
    gemm_body(hs, B, bias, C, N, DD, blockIdx.y * TBM, bn, cvt, sm);
}

// ---- output projection ----
__global__ __launch_bounds__(256)
void tgemm_o(const float* __restrict__ A, const float* __restrict__ Wo,
             const float* __restrict__ bo, float* __restrict__ C)
{
    extern __shared__ float sm[];
    gemm_body(A, Wo, bo, C, DD, DD, blockIdx.y * TBM, blockIdx.x * TBN, false, sm);
}

// ---------------- rope + vtrans (with sigma row permutation) + mask bias ------
// sigma: within each 8-row KV group, V column slot j holds position sig(j):
//   sig = [0,2,4,6,1,3,5,7]  (so position p stored at slot (p>>1)+(p&1)*4)
__global__ void post_kernel(const float* __restrict__ qin, float* __restrict__ qout,
                            const float* __restrict__ kin, float* __restrict__ kout,
                            const float* __restrict__ V, float* __restrict__ Vt,
                            const float* __restrict__ mask, float* __restrict__ mb)
{
    __shared__ float t[64 * 68];
    const int tid = threadIdx.x;

    if (blockIdx.x < 256) {
        // ---- vtrans part ----
        int bi = blockIdx.x;
        int kt  = bi & 31;
        int kvh = (bi >> 5) & 3;
        int b   = bi >> 7;
#pragma unroll
        for (int i = 0; i < 4; i++) {
            int f = tid + i * 256;
            int r = f >> 4, c = (f & 15) << 2;
            *(float4*)&t[r * 68 + c] =
                *(const float4*)(V + (size_t)(b * SS + kt * 64 + r) * (NKV * DH) + kvh * 64 + c);
        }
        __syncthreads();
        int d = tid >> 2;
        int g = tid & 3;
        int off = g * 16 + (g >> 1) * 4;
        float* out = Vt + ((size_t)(b * NKV + kvh) * DH + d) * VTROW + kt * PR + off;
#pragma unroll
        for (int s4 = 0; s4 < 16; s4 += 4) {
            float vals[4];
#pragma unroll
            for (int q = 0; q < 4; q++) {
                int c   = 4 * (s4 + q) + g;
                int jin = c & 7;
                int pin = (jin < 4) ? (2 * jin) : (2 * (jin - 4) + 1);
                int srow = (c & ~7) | pin;
                vals[q] = t[srow * 68 + d];
            }
            float4 w = make_float4(vals[0], vals[1], vals[2], vals[3]);
            *(float4*)(out + s4) = w;
        }
        return;
    }

    // ---- rope part ----
    int idx = (blockIdx.x - 256) * blockDim.x + tid;
    const int qTotal = MM * NH * 32;
    const int kTotal = MM * NKV * 32;
    if (idx >= qTotal + kTotal) {
        int i = idx - qTotal - kTotal;
        if (i < MM) mb[i] = (1.0f - mask[i]) * (-1e9f * LOG2E);
        return;
    }
    bool isQ = idx < qTotal;
    int nHeads = isQ ? NH : NKV;
    float scale = isQ ? (0.125f * LOG2E) : 1.0f;
    const float* in = isQ ? qin : kin;
    if (!isQ) idx -= qTotal;

    int i   = idx & 31;
    int h   = (idx >> 5) % nHeads;
    int row = idx / (nHeads * 32);
    int s   = row & (SS - 1);
    int b   = row >> 11;

    float ex  = -(float)(2 * i) / 64.0f;
    float inv = powf(10000.0f, ex);
    float ang = (float)s * inv;
    float sn, cs;
    sincosf(ang, &sn, &cs);

    const float* p = in + (size_t)row * (nHeads * 64) + h * 64;
    float x1 = p[i], x2 = p[i + 32];
    float y1 = f2tf((x1 * cs - x2 * sn) * scale);
    float y2 = f2tf((x1 * sn + x2 * cs) * scale);

    if (isQ) {
        float* q = qout + (size_t)row * (NH * 64) + h * 64;
        q[i] = y1; q[i + 32] = y2;
    } else {
        int g = i & 3;
        int off = g * 16 + (g >> 1) * 4;
        float* q = kout + ((size_t)(b * NKV + h) * SS + s) * PR;
        q[off + (i >> 2)]     = y1;
        q[off + (i >> 2) + 8] = y2;
    }
}

// ---------------- flash attention: register-resident P, split S chains ------
#define BQ 128
#define STG (64 * PR * 2 + 64)                  // K + V + mask per stage
#define ATTN_SMEM ((2 * STG + BQ * PR) * 4)     // ~111 KB

__global__ __launch_bounds__(128, 2)
void attn_mma_kernel(const float* __restrict__ Q,    // roped + 0.125*log2e + tf32
                     const float* __restrict__ Kp,   // permuted K
                     const float* __restrict__ Vt,   // transposed+sigma-permuted V
                     const float* __restrict__ MB,   // mask bias * log2e
                     float* __restrict__ O)          // ao (tf32-rounded on store)
{
    extern __shared__ float sm[];
    float* P = sm + 2 * STG;   // used only for Q staging

    const int qb = blockIdx.x, h = blockIdx.y, b = blockIdx.z;
    const int kvh = h >> 2;
    const int tid  = threadIdx.x;
    const int lane = tid & 31;
    const int warp = tid >> 5;
    const int gr   = lane >> 2;
    const int tig  = lane & 3;
    const int q0   = warp * 32;
    const int goff = tig * 16 + (tig >> 1) * 4;

    const float* Kbase = Kp + (size_t)(b * NKV + kvh) * SS * PR;
    const float* Vbase = Vt + (size_t)(b * NKV + kvh) * DH * VTROW;

    auto issue = [&](int kt, int bi) {
        float* Ks = sm + bi * STG;
        float* Vs = Ks + 64 * PR;
        float* Ms = Vs + 64 * PR;
#pragma unroll
        for (int i = 0; i < 8; i++) {
            int idx = tid + i * 128;
            int r = idx >> 4, c = idx & 15;
            int g = c >> 2, j = c & 3;
            int fo = g * 16 + (g >> 1) * 4 + 4 * j;
            CPA16(sm_u32(&Ks[r * PR + fo]), Kbase + (size_t)(kt * 64 + r) * PR + fo);
            CPA16(sm_u32(&Vs[r * PR + fo]), Vbase + (size_t)r * VTROW + kt * PR + fo);
        }
        if (tid < 16)
            CPA16(sm_u32(&Ms[tid * 4]), MB + b * SS + kt * 64 + tid * 4);
        CPC();
    };

    issue(0, 0);

    // stage Q tile and hoist fragments
#pragma unroll
    for (int i = 0; i < 16; i++) {
        int idx = tid + i * 128;
        int r = idx >> 4, c = (idx & 15) << 2;
        *(float4*)&P[r * PR + c] =
            *(const float4*)(Q + (size_t)(b * SS + qb * BQ + r) * DD + h * 64 + c);
    }
    __syncthreads();
    unsigned qa[2][8][4];
#pragma unroll
    for (int mt = 0; mt < 2; mt++)
#pragma unroll
        for (int ks = 0; ks < 8; ks++) {
            int r0 = q0 + mt * 16 + gr;
            qa[mt][ks][0] = __float_as_uint(P[r0 * PR + ks * 8 + tig]);
            qa[mt][ks][1] = __float_as_uint(P[(r0 + 8) * PR + ks * 8 + tig]);
            qa[mt][ks][2] = __float_as_uint(P[r0 * PR + ks * 8 + tig + 4]);
            qa[mt][ks][3] = __float_as_uint(P[(r0 + 8) * PR + ks * 8 + tig + 4]);
        }

    float o[2][8][4];
#pragma unroll
    for (int mt = 0; mt < 2; mt++)
#pragma unroll
        for (int nt = 0; nt < 8; nt++)
#pragma unroll
            for (int i = 0; i < 4; i++) o[mt][nt][i] = 0.f;
    float l[4] = {0.f, 0.f, 0.f, 0.f};

    const int NKT = SS / 64;
    for (int kt = 0; kt < NKT; kt++) {
        CPW0();
        __syncthreads();
        if (kt + 1 < NKT) issue(kt + 1, (kt + 1) & 1);

        float* Ks = sm + (kt & 1) * STG;
        float* Vs = Ks + 64 * PR;
        float* Ms = Vs + 64 * PR;

#pragma unroll
        for (int kb = 0; kb < 8; kb++) {
            // ---- S fragment for k-block kb: 4 independent chains of depth 4 ----
            const float* kbp = Ks + (kb * 8 + gr) * PR + goff;
            float kr[16];
            *(float4*)(kr)      = *(const float4*)(kbp);
            *(float4*)(kr + 4)  = *(const float4*)(kbp + 4);
            *(float4*)(kr + 8)  = *(const float4*)(kbp + 8);
            *(float4*)(kr + 12) = *(const float4*)(kbp + 12);

            float s0a[4] = {0.f, 0.f, 0.f, 0.f};
            float s0b[4] = {0.f, 0.f, 0.f, 0.f};
            float s1a[4] = {0.f, 0.f, 0.f, 0.f};
            float s1b[4] = {0.f, 0.f, 0.f, 0.f};
#pragma unroll
            for (int ks = 0; ks < 8; ks += 2) {
                unsigned be[2] = { __float_as_uint(kr[2 * ks]),
                                   __float_as_uint(kr[2 * ks + 1]) };
                unsigned bo[2] = { __float_as_uint(kr[2 * ks + 2]),
                                   __float_as_uint(kr[2 * ks + 3]) };
                mma8(s0a, qa[0][ks],     be, s0a);
                mma8(s1a, qa[1][ks],     be, s1a);
                mma8(s0b, qa[0][ks + 1], bo, s0b);
                mma8(s1b, qa[1][ks + 1], bo, s1b);
            }

            // ---- softmax -> register-resident A fragments ----
            float2 mbv = *(const float2*)(&Ms[kb * 8 + 2 * tig]);
            float a0f0 = ex2(s0a[0] + s0b[0] + mbv.x);
            float a0f1 = ex2(s0a[2] + s0b[2] + mbv.x);
            float a0f2 = ex2(s0a[1] + s0b[1] + mbv.y);
            float a0f3 = ex2(s0a[3] + s0b[3] + mbv.y);
            l[0] += a0f0 + a0f2;
            l[1] += a0f1 + a0f3;
            float a1f0 = ex2(s1a[0] + s1b[0] + mbv.x);
            float a1f1 = ex2(s1a[2] + s1b[2] + mbv.x);
            float a1f2 = ex2(s1a[1] + s1b[1] + mbv.y);
            float a1f3 = ex2(s1a[3] + s1b[3] + mbv.y);
            l[2] += a1f0 + a1f2;
            l[3] += a1f1 + a1f3;

            unsigned a0[4] = { __float_as_uint(a0f0), __float_as_uint(a0f1),
                               __float_as_uint(a0f2), __float_as_uint(a0f3) };
            unsigned a1[4] = { __float_as_uint(a1f0), __float_as_uint(a1f1),
                               __float_as_uint(a1f2), __float_as_uint(a1f3) };

            // ---- O += P(kb) @ V(kb) across all dh tiles ----
#pragma unroll
            for (int ntv = 0; ntv < 8; ntv++) {
                float2 vv = *(const float2*)(&Vs[(ntv * 8 + gr) * PR + goff + 2 * kb]);
                unsigned bfr2[2] = { __float_as_uint(vv.x), __float_as_uint(vv.y) };
                mma8(o[0][ntv], a0, bfr2, o[0][ntv]);
                mma8(o[1][ntv], a1, bfr2, o[1][ntv]);
            }
        }
    }

    // final l reduction
#pragma unroll
    for (int i = 0; i < 4; i++) {
        l[i] += __shfl_xor_sync(0xffffffffu, l[i], 1);
        l[i] += __shfl_xor_sync(0xffffffffu, l[i], 2);
    }

    // normalize + write (tf32-rounded — feeds the pure-copy output GEMM)
#pragma unroll
    for (int mt = 0; mt < 2; mt++) {
        float inv0 = 1.0f / l[mt * 2 + 0], inv1 = 1.0f / l[mt * 2 + 1];
        int rg = b * SS + qb * BQ + q0 + mt * 16 + gr;
#pragma unroll
        for (int nt = 0; nt < 8; nt++) {
            int col = h * 64 + nt * 8 + 2 * tig;
            *(float2*)(&O[(size_t)rg * DD + col]) =
                make_float2(f2tf(o[mt][nt][0] * inv0), f2tf(o[mt][nt][1] * inv0));
            *(float2*)(&O[(size_t)(rg + 8) * DD + col]) =
                make_float2(f2tf(o[mt][nt][2] * inv1), f2tf(o[mt][nt][3] * inv1));
        }
    }
}

// ---------------- launcher ----------------
extern "C" void kernel_launch(void* const* d_in, const int* in_sizes, int n_in,
                              void* d_out, int out_size)
{
    const float* hs   = (const float*)d_in[0];
    const float* mask = (const float*)d_in[1];
    const float* Wq   = (const float*)d_in[2];
    const float* bq   = (const float*)d_in[3];
    const float* Wk   = (const float*)d_in[4];
    const float* bk   = (const float*)d_in[5];
    const float* Wv   = (const float*)d_in[6];
    const float* bv   = (const float*)d_in[7];
    const float* Wo   = (const float*)d_in[8];
    const float* bo   = (const float*)d_in[9];
    float* out = (float*)d_out;

    float *q, *k, *v, *qr, *kr, *vt, *ao, *mb;
    float *hsr, *wq, *wk, *wv, *wo;
    cudaGetSymbolAddress((void**)&q,   g_q);
    cudaGetSymbolAddress((void**)&k,   g_k);
    cudaGetSymbolAddress((void**)&v,   g_v);
    cudaGetSymbolAddress((void**)&qr,  g_qr);
    cudaGetSymbolAddress((void**)&kr,  g_kr);
    cudaGetSymbolAddress((void**)&vt,  g_vt);
    cudaGetSymbolAddress((void**)&ao,  g_ao);
    cudaGetSymbolAddress((void**)&mb,  g_mb);
    cudaGetSymbolAddress((void**)&hsr, g_hsr);
    cudaGetSymbolAddress((void**)&wq,  g_wq);
    cudaGetSymbolAddress((void**)&wk,  g_wk);
    cudaGetSymbolAddress((void**)&wv,  g_wv);
    cudaGetSymbolAddress((void**)&wo,  g_wo);

    cudaFuncSetAttribute(proj_all, cudaFuncAttributeMaxDynamicSharedMemorySize, GSMEM);
    cudaFuncSetAttribute(tgemm_o,  cudaFuncAttributeMaxDynamicSharedMemorySize, GSMEM);
    cudaFuncSetAttribute(attn_mma_kernel, cudaFuncAttributeMaxDynamicSharedMemorySize, ATTN_SMEM);

    // tf32-round inputs once
    prep_kernel<<<6656, 256>>>((const float4*)hs, (const float4*)Wq, (const float4*)Wk,
                               (const float4*)Wv, (const float4*)Wo,
                               (float4*)hsr, (float4*)wq, (float4*)wk,
                               (float4*)wv, (float4*)wo);

    // Q/K/V projections in one launch (pure-copy cp.async tiles)
    proj_all<<<dim3(12, MM / TBM), 256, GSMEM>>>(hsr, wq, bq, wk, bk, wv, bv, q, k, v);

    // rope (q,k) + vtrans (sigma) + mask bias in one launch
    {
        int ropeBlocks = (MM * (NH + NKV) * 32 + MM + 255) / 256;
        post_kernel<<<256 + ropeBlocks, 256>>>(q, qr, k, kr, v, vt, mask, mb);
    }

    // attention
    attn_mma_kernel<<<dim3(SS / BQ, NH, BB), 128, ATTN_SMEM>>>(qr, kr, vt, mb, ao);

    // output projection
    tgemm_o<<<dim3(DD / TBN, MM / TBM), 256, GSMEM>>>(ao, wo, bo, out);
}

// round 16
// speedup vs baseline: 1.0193x; 1.0193x over previous
#include <cuda_runtime.h>
#include <math.h>

// Problem constants
#define BB 2
#define SS 2048
#define DD 1024
#define NH 16
#define NKV 4
#define DH 64
#define MM (BB*SS)   // 4096

// Permuted-row layout (4 groups of 16 floats at offsets 0,16,36,52; row stride 72)
#define PR 72
#define VTROW (32 * PR)

#define LOG2E 1.44269504088896340736f

// ---------------- scratch (16B aligned for cp.async) ----------------
__device__ __align__(16) float g_q  [MM * DD];
__device__ __align__(16) float g_k  [MM * NKV*DH];
__device__ __align__(16) float g_v  [MM * NKV*DH];
__device__ __align__(16) float g_qr [MM * DD];
__device__ __align__(16) float g_kr [BB*NKV*SS * PR];
__device__ __align__(16) float g_vt [BB*NKV*DH * VTROW];
__device__ __align__(16) float g_ao [MM * DD];
__device__ __align__(16) float g_mb [MM];
// tf32-pre-rounded copies of inputs
__device__ __align__(16) float g_hsr[MM * DD];
__device__ __align__(16) float g_wq [DD * DD];
__device__ __align__(16) float g_wk [DD * NKV*DH];
__device__ __align__(16) float g_wv [DD * NKV*DH];
__device__ __align__(16) float g_wo [DD * DD];

// ---------------- helpers ----------------
__device__ __forceinline__ float f2tf(float x) {
    unsigned u;
    asm("cvt.rna.tf32.f32 %0, %1;" : "=r"(u) : "f"(x));
    return __uint_as_float(u);
}

__device__ __forceinline__ float ex2(float x) {
    float y;
    asm("ex2.approx.f32 %0, %1;" : "=f"(y) : "f"(x));
    return y;
}

__device__ __forceinline__ void mma8(float* d, const unsigned* a, const unsigned* b,
                                     const float* c) {
    asm volatile(
        "mma.sync.aligned.m16n8k8.row.col.f32.tf32.tf32.f32 "
        "{%0,%1,%2,%3}, {%4,%5,%6,%7}, {%8,%9}, {%10,%11,%12,%13};"
        : "=f"(d[0]), "=f"(d[1]), "=f"(d[2]), "=f"(d[3])
        : "r"(a[0]), "r"(a[1]), "r"(a[2]), "r"(a[3]),
          "r"(b[0]), "r"(b[1]),
          "f"(c[0]), "f"(c[1]), "f"(c[2]), "f"(c[3]));
}

__device__ __forceinline__ unsigned sm_u32(const void* p) {
    unsigned a;
    asm("{ .reg .u64 t; cvta.to.shared.u64 t, %1; cvt.u32.u64 %0, t; }"
        : "=r"(a) : "l"(p));
    return a;
}
#define CPA16(d, s) asm volatile("cp.async.cg.shared.global [%0], [%1], 16;" :: "r"(d), "l"(s))
#define CPC()  asm volatile("cp.async.commit_group;")
#define CPW0() asm volatile("cp.async.wait_group 0;" ::: "memory")

// ---------------- prep: tf32-round inputs once ----------------
__global__ void prep_kernel(const float4* __restrict__ hs, const float4* __restrict__ Wq,
                            const float4* __restrict__ Wk, const float4* __restrict__ Wv,
                            const float4* __restrict__ Wo,
                            float4* __restrict__ hsr, float4* __restrict__ wq,
                            float4* __restrict__ wk,  float4* __restrict__ wv,
                            float4* __restrict__ wo)
{
    long i = (long)blockIdx.x * 256 + threadIdx.x;
    const float4* src; float4* dst;
    if (i < 1048576)            { src = hs; dst = hsr; }
    else if (i < 1310720)       { i -= 1048576; src = Wq; dst = wq; }
    else if (i < 1376256)       { i -= 1310720; src = Wk; dst = wk; }
    else if (i < 1441792)       { i -= 1376256; src = Wv; dst = wv; }
    else if (i < 1703936)       { i -= 1441792; src = Wo; dst = wo; }
    else return;
    float4 v = src[i];
    v.x = f2tf(v.x); v.y = f2tf(v.y); v.z = f2tf(v.z); v.w = f2tf(v.w);
    dst[i] = v;
}

// ---------------- tf32 GEMM body: cp.async ping-pong, pure-copy tiles ----------
#define TBM 128
#define TBN 128
#define TBK 32
#define ASTR 36
#define BSTR 136
#define GSMEM ((2 * TBM * ASTR + 2 * TBK * BSTR) * 4)   // 70 KB

__device__ __forceinline__ void gemm_body(
    const float* __restrict__ A, const float* __restrict__ B,
    const float* __restrict__ bias, float* __restrict__ C,
    int N, int K, int bm, int bn, bool cvtOut, float* sm)
{
    float* As = sm;
    float* Bs = sm + 2 * TBM * ASTR;

    const int tid  = threadIdx.x;
    const int lane = tid & 31;
    const int warp = tid >> 5;
    const int gr   = lane >> 2;
    const int tig  = lane & 3;
    const int warp_m = (warp & 1) * 64;
    const int warp_n = (warp >> 1) * 32;

    float acc[4][4][4];
#pragma unroll
    for (int mt = 0; mt < 4; mt++)
#pragma unroll
        for (int nt = 0; nt < 4; nt++)
#pragma unroll
            for (int i = 0; i < 4; i++) acc[mt][nt][i] = 0.f;

    auto issue = [&](int t) {
        int k0 = t * TBK;
        int bi = t & 1;
        float* Asb = As + bi * TBM * ASTR;
        float* Bsb = Bs + bi * TBK * BSTR;
#pragma unroll
        for (int i = 0; i < 4; i++) {
            int idx = tid + i * 256;
            int am = idx >> 3, ac = (idx & 7) << 2;
            CPA16(sm_u32(&Asb[am * ASTR + ac]), A + (size_t)(bm + am) * K + k0 + ac);
            int bk = idx >> 5, bnn = (idx & 31) << 2;
            CPA16(sm_u32(&Bsb[bk * BSTR + bnn]), B + (size_t)(k0 + bk) * N + bn + bnn);
        }
        CPC();
    };

    const int T = K / TBK;
    issue(0);

    for (int t = 0; t < T; t++) {
        CPW0();
        __syncthreads();
        if (t + 1 < T) issue(t + 1);

        const float* Asb = As + (t & 1) * TBM * ASTR;
        const float* Bsb = Bs + (t & 1) * TBK * BSTR;
#pragma unroll
        for (int ks = 0; ks < 4; ks++) {
            int kk = ks * 8;
            unsigned afr[4][4], bfr[4][2];
#pragma unroll
            for (int mt = 0; mt < 4; mt++) {
                int r0 = warp_m + mt * 16 + gr;
                afr[mt][0] = __float_as_uint(Asb[r0 * ASTR + kk + tig]);
                afr[mt][1] = __float_as_uint(Asb[(r0 + 8) * ASTR + kk + tig]);
                afr[mt][2] = __float_as_uint(Asb[r0 * ASTR + kk + tig + 4]);
                afr[mt][3] = __float_as_uint(Asb[(r0 + 8) * ASTR + kk + tig + 4]);
            }
#pragma unroll
            for (int nt = 0; nt < 4; nt++) {
                int c0 = warp_n + nt * 8 + gr;
                bfr[nt][0] = __float_as_uint(Bsb[(kk + tig) * BSTR + c0]);
                bfr[nt][1] = __float_as_uint(Bsb[(kk + tig + 4) * BSTR + c0]);
            }
#pragma unroll
            for (int mt = 0; mt < 4; mt++)
#pragma unroll
                for (int nt = 0; nt < 4; nt++)
                    mma8(acc[mt][nt], afr[mt], bfr[nt], acc[mt][nt]);
        }
    }

#pragma unroll
    for (int mt = 0; mt < 4; mt++) {
        int r0 = bm + warp_m + mt * 16 + gr;
#pragma unroll
        for (int nt = 0; nt < 4; nt++) {
            int c0 = bn + warp_n + nt * 8 + 2 * tig;
            float bx = bias[c0], by = bias[c0 + 1];
            float2 o0 = make_float2(acc[mt][nt][0] + bx, acc[mt][nt][1] + by);
            float2 o1 = make_float2(acc[mt][nt][2] + bx, acc[mt][nt][3] + by);
            if (cvtOut) {
                o0.x = f2tf(o0.x); o0.y = f2tf(o0.y);
                o1.x = f2tf(o1.x); o1.y = f2tf(o1.y);
            }
            *(float2*)(&C[(size_t)r0 * N + c0]) = o0;
            *(float2*)(&C[(size_t)(r0 + 8) * N + c0]) = o1;
        }
    }
}

// ---- merged Q/K/V projections: grid (12, 32) ----
__global__ __launch_bounds__(256)
void proj_all(const float* __restrict__ hs,
              const float* __restrict__ Wq, const float* __restrict__ bq,
              const float* __restrict__ Wk, const float* __restrict__ bk,
              const float* __restrict__ Wv, const float* __restrict__ bv,
              float* __restrict__ q, float* __restrict__ k, float* __restrict__ v)
{
    extern __shared__ float sm[];
    int bx = blockIdx.x;
    const float *B, *bias; float* C; int N, bn; bool cvt;
    if (bx < 8)       { B = Wq; bias = bq; C = q; N = DD;       bn = bx * TBN;        cvt = false; }
    else if (bx < 10) { B = Wk; bias = bk; C = k; N = NKV * DH; bn = (bx - 8) * TBN;  cvt = false; }
    else              { B = Wv; bias = bv; C = v; N = NKV * DH; bn = (bx - 10) * TBN; cvt = true;  }
    gemm_body(hs, B, bias, C, N, DD, blockIdx.y * TBM, bn, cvt, sm);
}

// ---- output projection ----
__global__ __launch_bounds__(256)
void tgemm_o(const float* __restrict__ A, const float* __restrict__ Wo,
             const float* __restrict__ bo, float* __restrict__ C)
{
    extern __shared__ float sm[];
    gemm_body(A, Wo, bo, C, DD, DD, blockIdx.y * TBM, blockIdx.x * TBN, false, sm);
}

// ---------------- rope + vtrans (with sigma row permutation) + mask bias ------
// sigma: within each 8-row KV group, V column slot j holds position sig(j):
//   sig = [0,2,4,6,1,3,5,7]  (so position p stored at slot (p>>1)+(p&1)*4)
__global__ void post_kernel(const float* __restrict__ qin, float* __restrict__ qout,
                            const float* __restrict__ kin, float* __restrict__ kout,
                            const float* __restrict__ V, float* __restrict__ Vt,
                            const float* __restrict__ mask, float* __restrict__ mb)
{
    __shared__ float t[64 * 68];
    const int tid = threadIdx.x;

    if (blockIdx.x < 256) {
        // ---- vtrans part ----
        int bi = blockIdx.x;
        int kt  = bi & 31;
        int kvh = (bi >> 5) & 3;
        int b   = bi >> 7;
#pragma unroll
        for (int i = 0; i < 4; i++) {
            int f = tid + i * 256;
            int r = f >> 4, c = (f & 15) << 2;
            *(float4*)&t[r * 68 + c] =
                *(const float4*)(V + (size_t)(b * SS + kt * 64 + r) * (NKV * DH) + kvh * 64 + c);
        }
        __syncthreads();
        int d = tid >> 2;
        int g = tid & 3;
        int off = g * 16 + (g >> 1) * 4;
        float* out = Vt + ((size_t)(b * NKV + kvh) * DH + d) * VTROW + kt * PR + off;
#pragma unroll
        for (int s4 = 0; s4 < 16; s4 += 4) {
            float vals[4];
#pragma unroll
            for (int q = 0; q < 4; q++) {
                int c   = 4 * (s4 + q) + g;
                int jin = c & 7;
                int pin = (jin < 4) ? (2 * jin) : (2 * (jin - 4) + 1);
                int srow = (c & ~7) | pin;
                vals[q] = t[srow * 68 + d];
            }
            float4 w = make_float4(vals[0], vals[1], vals[2], vals[3]);
            *(float4*)(out + s4) = w;
        }
        return;
    }

    // ---- rope part ----
    int idx = (blockIdx.x - 256) * blockDim.x + tid;
    const int qTotal = MM * NH * 32;
    const int kTotal = MM * NKV * 32;
    if (idx >= qTotal + kTotal) {
        int i = idx - qTotal - kTotal;
        if (i < MM) mb[i] = (1.0f - mask[i]) * (-1e9f * LOG2E);
        return;
    }
    bool isQ = idx < qTotal;
    int nHeads = isQ ? NH : NKV;
    float scale = isQ ? (0.125f * LOG2E) : 1.0f;
    const float* in = isQ ? qin : kin;
    if (!isQ) idx -= qTotal;

    int i   = idx & 31;
    int h   = (idx >> 5) % nHeads;
    int row = idx / (nHeads * 32);
    int s   = row & (SS - 1);
    int b   = row >> 11;

    float ex  = -(float)(2 * i) / 64.0f;
    float inv = powf(10000.0f, ex);
    float ang = (float)s * inv;
    float sn, cs;
    sincosf(ang, &sn, &cs);

    const float* p = in + (size_t)row * (nHeads * 64) + h * 64;
    float x1 = p[i], x2 = p[i + 32];
    float y1 = f2tf((x1 * cs - x2 * sn) * scale);
    float y2 = f2tf((x1 * sn + x2 * cs) * scale);

    if (isQ) {
        float* q = qout + (size_t)row * (NH * 64) + h * 64;
        q[i] = y1; q[i + 32] = y2;
    } else {
        int g = i & 3;
        int off = g * 16 + (g >> 1) * 4;
        float* q = kout + ((size_t)(b * NKV + h) * SS + s) * PR;
        q[off + (i >> 2)]     = y1;
        q[off + (i >> 2) + 8] = y2;
    }
}

// ---------------- flash attention: register-resident P, kr software pipeline --
#define BQ 128
#define STG (64 * PR * 2 + 64)                  // K + V + mask per stage
#define ATTN_SMEM ((2 * STG + BQ * PR) * 4)     // ~111 KB

__global__ __launch_bounds__(128, 2)
void attn_mma_kernel(const float* __restrict__ Q,    // roped + 0.125*log2e + tf32
                     const float* __restrict__ Kp,   // permuted K
                     const float* __restrict__ Vt,   // transposed+sigma-permuted V
                     const float* __restrict__ MB,   // mask bias * log2e
                     float* __restrict__ O)          // ao (tf32-rounded on store)
{
    extern __shared__ float sm[];
    float* P = sm + 2 * STG;   // used only for Q staging

    const int qb = blockIdx.x, h = blockIdx.y, b = blockIdx.z;
    const int kvh = h >> 2;
    const int tid  = threadIdx.x;
    const int lane = tid & 31;
    const int warp = tid >> 5;
    const int gr   = lane >> 2;
    const int tig  = lane & 3;
    const int q0   = warp * 32;
    const int goff = tig * 16 + (tig >> 1) * 4;

    const float* Kbase = Kp + (size_t)(b * NKV + kvh) * SS * PR;
    const float* Vbase = Vt + (size_t)(b * NKV + kvh) * DH * VTROW;

    auto issue = [&](int kt, int bi) {
        float* Ks = sm + bi * STG;
        float* Vs = Ks + 64 * PR;
        float* Ms = Vs + 64 * PR;
#pragma unroll
        for (int i = 0; i < 8; i++) {
            int idx = tid + i * 128;
            int r = idx >> 4, c = idx & 15;
            int g = c >> 2, j = c & 3;
            int fo = g * 16 + (g >> 1) * 4 + 4 * j;
            CPA16(sm_u32(&Ks[r * PR + fo]), Kbase + (size_t)(kt * 64 + r) * PR + fo);
            CPA16(sm_u32(&Vs[r * PR + fo]), Vbase + (size_t)r * VTROW + kt * PR + fo);
        }
        if (tid < 16)
            CPA16(sm_u32(&Ms[tid * 4]), MB + b * SS + kt * 64 + tid * 4);
        CPC();
    };

    issue(0, 0);

    // stage Q tile and hoist fragments
#pragma unroll
    for (int i = 0; i < 16; i++) {
        int idx = tid + i * 128;
        int r = idx >> 4, c = (idx & 15) << 2;
        *(float4*)&P[r * PR + c] =
            *(const float4*)(Q + (size_t)(b * SS + qb * BQ + r) * DD + h * 64 + c);
    }
    __syncthreads();
    unsigned qa[2][8][4];
#pragma unroll
    for (int mt = 0; mt < 2; mt++)
#pragma unroll
        for (int ks = 0; ks < 8; ks++) {
            int r0 = q0 + mt * 16 + gr;
            qa[mt][ks][0] = __float_as_uint(P[r0 * PR + ks * 8 + tig]);
            qa[mt][ks][1] = __float_as_uint(P[(r0 + 8) * PR + ks * 8 + tig]);
            qa[mt][ks][2] = __float_as_uint(P[r0 * PR + ks * 8 + tig + 4]);
            qa[mt][ks][3] = __float_as_uint(P[(r0 + 8) * PR + ks * 8 + tig + 4]);
        }

    float o[2][8][4];
#pragma unroll
    for (int mt = 0; mt < 2; mt++)
#pragma unroll
        for (int nt = 0; nt < 8; nt++)
#pragma unroll
            for (int i = 0; i < 4; i++) o[mt][nt][i] = 0.f;
    float l[4] = {0.f, 0.f, 0.f, 0.f};

    const int NKT = SS / 64;
    for (int kt = 0; kt < NKT; kt++) {
        CPW0();
        __syncthreads();
        if (kt + 1 < NKT) issue(kt + 1, (kt + 1) & 1);

        float* Ks = sm + (kt & 1) * STG;
        float* Vs = Ks + 64 * PR;
        float* Ms = Vs + 64 * PR;

        // prime kr for kb = 0
        float kr[16];
        {
            const float* kbp = Ks + gr * PR + goff;
            *(float4*)(kr)      = *(const float4*)(kbp);
            *(float4*)(kr + 4)  = *(const float4*)(kbp + 4);
            *(float4*)(kr + 8)  = *(const float4*)(kbp + 8);
            *(float4*)(kr + 12) = *(const float4*)(kbp + 12);
        }

#pragma unroll
        for (int kb = 0; kb < 8; kb++) {
            // ---- S fragment for k-block kb ----
            float s0[4] = {0.f, 0.f, 0.f, 0.f};
            float s1[4] = {0.f, 0.f, 0.f, 0.f};
#pragma unroll
            for (int ks = 0; ks < 8; ks++) {
                unsigned bfr[2] = { __float_as_uint(kr[2 * ks]),
                                    __float_as_uint(kr[2 * ks + 1]) };
                mma8(s0, qa[0][ks], bfr, s0);
                mma8(s1, qa[1][ks], bfr, s1);
            }

            // ---- prefetch kr for kb+1 (overlaps softmax + PV below) ----
            float krn[16];
            if (kb < 7) {
                const float* kbn = Ks + ((kb + 1) * 8 + gr) * PR + goff;
                *(float4*)(krn)      = *(const float4*)(kbn);
                *(float4*)(krn + 4)  = *(const float4*)(kbn + 4);
                *(float4*)(krn + 8)  = *(const float4*)(kbn + 8);
                *(float4*)(krn + 12) = *(const float4*)(kbn + 12);
            }

            // ---- softmax -> register-resident A fragments ----
            float2 mbv = *(const float2*)(&Ms[kb * 8 + 2 * tig]);
            float a0f0 = ex2(s0[0] + mbv.x);
            float a0f1 = ex2(s0[2] + mbv.x);
            float a0f2 = ex2(s0[1] + mbv.y);
            float a0f3 = ex2(s0[3] + mbv.y);
            l[0] += a0f0 + a0f2;
            l[1] += a0f1 + a0f3;
            float a1f0 = ex2(s1[0] + mbv.x);
            float a1f1 = ex2(s1[2] + mbv.x);
            float a1f2 = ex2(s1[1] + mbv.y);
            float a1f3 = ex2(s1[3] + mbv.y);
            l[2] += a1f0 + a1f2;
            l[3] += a1f1 + a1f3;

            unsigned a0[4] = { __float_as_uint(a0f0), __float_as_uint(a0f1),
                               __float_as_uint(a0f2), __float_as_uint(a0f3) };
            unsigned a1[4] = { __float_as_uint(a1f0), __float_as_uint(a1f1),
                               __float_as_uint(a1f2), __float_as_uint(a1f3) };

            // ---- O += P(kb) @ V(kb) across all dh tiles ----
#pragma unroll
            for (int ntv = 0; ntv < 8; ntv++) {
                float2 vv = *(const float2*)(&Vs[(ntv * 8 + gr) * PR + goff + 2 * kb]);
                unsigned bfr2[2] = { __float_as_uint(vv.x), __float_as_uint(vv.y) };
                mma8(o[0][ntv], a0, bfr2, o[0][ntv]);
                mma8(o[1][ntv], a1, bfr2, o[1][ntv]);
            }

            if (kb < 7) {
#pragma unroll
                for (int i = 0; i < 16; i++) kr[i] = krn[i];
            }
        }
    }

    // final l reduction
#pragma unroll
    for (int i = 0; i < 4; i++) {
        l[i] += __shfl_xor_sync(0xffffffffu, l[i], 1);
        l[i] += __shfl_xor_sync(0xffffffffu, l[i], 2);
    }

    // normalize + write (tf32-rounded — feeds the pure-copy output GEMM)
#pragma unroll
    for (int mt = 0; mt < 2; mt++) {
        float inv0 = 1.0f / l[mt * 2 + 0], inv1 = 1.0f / l[mt * 2 + 1];
        int rg = b * SS + qb * BQ + q0 + mt * 16 + gr;
#pragma unroll
        for (int nt = 0; nt < 8; nt++) {
            int col = h * 64 + nt * 8 + 2 * tig;
            *(float2*)(&O[(size_t)rg * DD + col]) =
                make_float2(f2tf(o[mt][nt][0] * inv0), f2tf(o[mt][nt][1] * inv0));
            *(float2*)(&O[(size_t)(rg + 8) * DD + col]) =
                make_float2(f2tf(o[mt][nt][2] * inv1), f2tf(o[mt][nt][3] * inv1));
        }
    }
}

// ---------------- launcher ----------------
extern "C" void kernel_launch(void* const* d_in, const int* in_sizes, int n_in,
                              void* d_out, int out_size)
{
    const float* hs   = (const float*)d_in[0];
    const float* mask = (const float*)d_in[1];
    const float* Wq   = (const float*)d_in[2];
    const float* bq   = (const float*)d_in[3];
    const float* Wk   = (const float*)d_in[4];
    const float* bk   = (const float*)d_in[5];
    const float* Wv   = (const float*)d_in[6];
    const float* bv   = (const float*)d_in[7];
    const float* Wo   = (const float*)d_in[8];
    const float* bo   = (const float*)d_in[9];
    float* out = (float*)d_out;

    float *q, *k, *v, *qr, *kr, *vt, *ao, *mb;
    float *hsr, *wq, *wk, *wv, *wo;
    cudaGetSymbolAddress((void**)&q,   g_q);
    cudaGetSymbolAddress((void**)&k,   g_k);
    cudaGetSymbolAddress((void**)&v,   g_v);
    cudaGetSymbolAddress((void**)&qr,  g_qr);
    cudaGetSymbolAddress((void**)&kr,  g_kr);
    cudaGetSymbolAddress((void**)&vt,  g_vt);
    cudaGetSymbolAddress((void**)&ao,  g_ao);
    cudaGetSymbolAddress((void**)&mb,  g_mb);
    cudaGetSymbolAddress((void**)&hsr, g_hsr);
    cudaGetSymbolAddress((void**)&wq,  g_wq);
    cudaGetSymbolAddress((void**)&wk,  g_wk);
    cudaGetSymbolAddress((void**)&wv,  g_wv);
    cudaGetSymbolAddress((void**)&wo,  g_wo);

    cudaFuncSetAttribute(proj_all, cudaFuncAttributeMaxDynamicSharedMemorySize, GSMEM);
    cudaFuncSetAttribute(tgemm_o,  cudaFuncAttributeMaxDynamicSharedMemorySize, GSMEM);
    cudaFuncSetAttribute(attn_mma_kernel, cudaFuncAttributeMaxDynamicSharedMemorySize, ATTN_SMEM);

    // tf32-round inputs once
    prep_kernel<<<6656, 256>>>((const float4*)hs, (const float4*)Wq, (const float4*)Wk,
                               (const float4*)Wv, (const float4*)Wo,
                               (float4*)hsr, (float4*)wq, (float4*)wk,
                               (float4*)wv, (float4*)wo);

    // Q/K/V projections in one launch (pure-copy cp.async tiles)
    proj_all<<<dim3(12, MM / TBM), 256, GSMEM>>>(hsr, wq, bq, wk, bk, wv, bv, q, k, v);

    // rope (q,k) + vtrans (sigma) + mask bias in one launch
    {
        int ropeBlocks = (MM * (NH + NKV) * 32 + MM + 255) / 256;
        post_kernel<<<256 + ropeBlocks, 256>>>(q, qr, k, kr, v, vt, mask, mb);
    }

    // attention
    attn_mma_kernel<<<dim3(SS / BQ, NH, BB), 128, ATTN_SMEM>>>(qr, kr, vt, mb, ao);

    // output projection
    tgemm_o<<<dim3(DD / TBN, MM / TBM), 256, GSMEM>>>(ao, wo, bo, out);
}

// round 17
// speedup vs baseline: 1.0465x; 1.0266x over previous
#include <cuda_runtime.h>
#include <math.h>

// Problem constants
#define BB 2
#define SS 2048
#define DD 1024
#define NH 16
#define NKV 4
#define DH 64
#define MM (BB*SS)   // 4096

// Permuted-row layout (4 groups of 16 floats at offsets 0,16,36,52; row stride 72)
#define PR 72
#define VTROW (32 * PR)

#define LOG2E 1.44269504088896340736f

// ---------------- scratch (16B aligned for cp.async) ----------------
__device__ __align__(16) float g_q  [MM * DD];
__device__ __align__(16) float g_k  [MM * NKV*DH];
__device__ __align__(16) float g_v  [MM * NKV*DH];
__device__ __align__(16) float g_kr [BB*NKV*SS * PR];
__device__ __align__(16) float g_vt [BB*NKV*DH * VTROW];
__device__ __align__(16) float g_ao [MM * DD];
__device__ __align__(16) float g_mb [MM];
__device__ __align__(16) float g_lut[SS * 64];      // cos at [s*64+i], sin at [s*64+32+i]
// tf32-pre-rounded copies of inputs
__device__ __align__(16) float g_hsr[MM * DD];
__device__ __align__(16) float g_wq [DD * DD];
__device__ __align__(16) float g_wk [DD * NKV*DH];
__device__ __align__(16) float g_wv [DD * NKV*DH];
__device__ __align__(16) float g_wo [DD * DD];

// ---------------- helpers ----------------
__device__ __forceinline__ float f2tf(float x) {
    unsigned u;
    asm("cvt.rna.tf32.f32 %0, %1;" : "=r"(u) : "f"(x));
    return __uint_as_float(u);
}

__device__ __forceinline__ float ex2(float x) {
    float y;
    asm("ex2.approx.f32 %0, %1;" : "=f"(y) : "f"(x));
    return y;
}

__device__ __forceinline__ void mma8(float* d, const unsigned* a, const unsigned* b,
                                     const float* c) {
    asm volatile(
        "mma.sync.aligned.m16n8k8.row.col.f32.tf32.tf32.f32 "
        "{%0,%1,%2,%3}, {%4,%5,%6,%7}, {%8,%9}, {%10,%11,%12,%13};"
        : "=f"(d[0]), "=f"(d[1]), "=f"(d[2]), "=f"(d[3])
        : "r"(a[0]), "r"(a[1]), "r"(a[2]), "r"(a[3]),
          "r"(b[0]), "r"(b[1]),
          "f"(c[0]), "f"(c[1]), "f"(c[2]), "f"(c[3]));
}

__device__ __forceinline__ unsigned sm_u32(const void* p) {
    unsigned a;
    asm("{ .reg .u64 t; cvta.to.shared.u64 t, %1; cvt.u32.u64 %0, t; }"
        : "=r"(a) : "l"(p));
    return a;
}
#define CPA16(d, s) asm volatile("cp.async.cg.shared.global [%0], [%1], 16;" :: "r"(d), "l"(s))
#define CPC()  asm volatile("cp.async.commit_group;")
#define CPW0() asm volatile("cp.async.wait_group 0;" ::: "memory")

// ---------------- prep: tf32-round inputs + rope LUT ----------------
// float4 segments: hs 1048576 | Wq 262144 | Wk 65536 | Wv 65536 | Wo 262144 = 1703936
// then 65536 scalar LUT tasks (s,i)
__global__ void prep_kernel(const float4* __restrict__ hs, const float4* __restrict__ Wq,
                            const float4* __restrict__ Wk, const float4* __restrict__ Wv,
                            const float4* __restrict__ Wo,
                            float4* __restrict__ hsr, float4* __restrict__ wq,
                            float4* __restrict__ wk,  float4* __restrict__ wv,
                            float4* __restrict__ wo,  float* __restrict__ lut)
{
    long i = (long)blockIdx.x * 256 + threadIdx.x;
    if (i >= 1703936) {
        long j = i - 1703936;
        if (j < SS * 32) {
            int s  = (int)(j >> 5);
            int ii = (int)(j & 31);
            float ex  = -(float)(2 * ii) / 64.0f;
            float inv = powf(10000.0f, ex);
            float ang = (float)s * inv;
            float sn, cs;
            sincosf(ang, &sn, &cs);
            lut[s * 64 + ii]      = cs;
            lut[s * 64 + 32 + ii] = sn;
        }
        return;
    }
    const float4* src; float4* dst;
    if (i < 1048576)            { src = hs; dst = hsr; }
    else if (i < 1310720)       { i -= 1048576; src = Wq; dst = wq; }
    else if (i < 1376256)       { i -= 1310720; src = Wk; dst = wk; }
    else if (i < 1441792)       { i -= 1376256; src = Wv; dst = wv; }
    else                        { i -= 1441792; src = Wo; dst = wo; }
    float4 v = src[i];
    v.x = f2tf(v.x); v.y = f2tf(v.y); v.z = f2tf(v.z); v.w = f2tf(v.w);
    dst[i] = v;
}

// ---------------- tf32 GEMM body: cp.async ping-pong, pure-copy tiles ----------
#define TBM 128
#define TBN 128
#define TBK 32
#define ASTR 36
#define BSTR 136
#define GSMEM ((2 * TBM * ASTR + 2 * TBK * BSTR) * 4)   // 70 KB

__device__ __forceinline__ void gemm_body(
    const float* __restrict__ A, const float* __restrict__ B,
    const float* __restrict__ bias, float* __restrict__ C,
    int N, int K, int bm, int bn, bool cvtOut, float* sm)
{
    float* As = sm;
    float* Bs = sm + 2 * TBM * ASTR;

    const int tid  = threadIdx.x;
    const int lane = tid & 31;
    const int warp = tid >> 5;
    const int gr   = lane >> 2;
    const int tig  = lane & 3;
    const int warp_m = (warp & 1) * 64;
    const int warp_n = (warp >> 1) * 32;

    float acc[4][4][4];
#pragma unroll
    for (int mt = 0; mt < 4; mt++)
#pragma unroll
        for (int nt = 0; nt < 4; nt++)
#pragma unroll
            for (int i = 0; i < 4; i++) acc[mt][nt][i] = 0.f;

    auto issue = [&](int t) {
        int k0 = t * TBK;
        int bi = t & 1;
        float* Asb = As + bi * TBM * ASTR;
        float* Bsb = Bs + bi * TBK * BSTR;
#pragma unroll
        for (int i = 0; i < 4; i++) {
            int idx = tid + i * 256;
            int am = idx >> 3, ac = (idx & 7) << 2;
            CPA16(sm_u32(&Asb[am * ASTR + ac]), A + (size_t)(bm + am) * K + k0 + ac);
            int bk = idx >> 5, bnn = (idx & 31) << 2;
            CPA16(sm_u32(&Bsb[bk * BSTR + bnn]), B + (size_t)(k0 + bk) * N + bn + bnn);
        }
        CPC();
    };

    const int T = K / TBK;
    issue(0);

    for (int t = 0; t < T; t++) {
        CPW0();
        __syncthreads();
        if (t + 1 < T) issue(t + 1);

        const float* Asb = As + (t & 1) * TBM * ASTR;
        const float* Bsb = Bs + (t & 1) * TBK * BSTR;
#pragma unroll
        for (int ks = 0; ks < 4; ks++) {
            int kk = ks * 8;
            unsigned afr[4][4], bfr[4][2];
#pragma unroll
            for (int mt = 0; mt < 4; mt++) {
                int r0 = warp_m + mt * 16 + gr;
                afr[mt][0] = __float_as_uint(Asb[r0 * ASTR + kk + tig]);
                afr[mt][1] = __float_as_uint(Asb[(r0 + 8) * ASTR + kk + tig]);
                afr[mt][2] = __float_as_uint(Asb[r0 * ASTR + kk + tig + 4]);
                afr[mt][3] = __float_as_uint(Asb[(r0 + 8) * ASTR + kk + tig + 4]);
            }
#pragma unroll
            for (int nt = 0; nt < 4; nt++) {
                int c0 = warp_n + nt * 8 + gr;
                bfr[nt][0] = __float_as_uint(Bsb[(kk + tig) * BSTR + c0]);
                bfr[nt][1] = __float_as_uint(Bsb[(kk + tig + 4) * BSTR + c0]);
            }
#pragma unroll
            for (int mt = 0; mt < 4; mt++)
#pragma unroll
                for (int nt = 0; nt < 4; nt++)
                    mma8(acc[mt][nt], afr[mt], bfr[nt], acc[mt][nt]);
        }
    }

#pragma unroll
    for (int mt = 0; mt < 4; mt++) {
        int r0 = bm + warp_m + mt * 16 + gr;
#pragma unroll
        for (int nt = 0; nt < 4; nt++) {
            int c0 = bn + warp_n + nt * 8 + 2 * tig;
            float bx = bias[c0], by = bias[c0 + 1];
            float2 o0 = make_float2(acc[mt][nt][0] + bx, acc[mt][nt][1] + by);
            float2 o1 = make_float2(acc[mt][nt][2] + bx, acc[mt][nt][3] + by);
            if (cvtOut) {
                o0.x = f2tf(o0.x); o0.y = f2tf(o0.y);
                o1.x = f2tf(o1.x); o1.y = f2tf(o1.y);
            }
            *(float2*)(&C[(size_t)r0 * N + c0]) = o0;
            *(float2*)(&C[(size_t)(r0 + 8) * N + c0]) = o1;
        }
    }
}

// ---- merged Q/K/V projections: grid (12, 32) ----
__global__ __launch_bounds__(256)
void proj_all(const float* __restrict__ hs,
              const float* __restrict__ Wq, const float* __restrict__ bq,
              const float* __restrict__ Wk, const float* __restrict__ bk,
              const float* __restrict__ Wv, const float* __restrict__ bv,
              float* __restrict__ q, float* __restrict__ k, float* __restrict__ v)
{
    extern __shared__ float sm[];
    int bx = blockIdx.x;
    const float *B, *bias; float* C; int N, bn; bool cvt;
    if (bx < 8)       { B = Wq; bias = bq; C = q; N = DD;       bn = bx * TBN;        cvt = false; }
    else if (bx < 10) { B = Wk; bias = bk; C = k; N = NKV * DH; bn = (bx - 8) * TBN;  cvt = false; }
    else              { B = Wv; bias = bv; C = v; N = NKV * DH; bn = (bx - 10) * TBN; cvt = true;  }
    gemm_body(hs, B, bias, C, N, DD, blockIdx.y * TBM, bn, cvt, sm);
}

// ---- output projection ----
__global__ __launch_bounds__(256)
void tgemm_o(const float* __restrict__ A, const float* __restrict__ Wo,
             const float* __restrict__ bo, float* __restrict__ C)
{
    extern __shared__ float sm[];
    gemm_body(A, Wo, bo, C, DD, DD, blockIdx.y * TBM, blockIdx.x * TBN, false, sm);
}

// ---------------- K-rope (LUT) + vtrans (sigma) + mask bias, one launch ------
__global__ void post_kernel(const float* __restrict__ kin, float* __restrict__ kout,
                            const float* __restrict__ V, float* __restrict__ Vt,
                            const float* __restrict__ mask, float* __restrict__ mb,
                            const float* __restrict__ lut)
{
    __shared__ float t[64 * 68];
    const int tid = threadIdx.x;

    if (blockIdx.x < 256) {
        // ---- vtrans part ----
        int bi = blockIdx.x;
        int kt  = bi & 31;
        int kvh = (bi >> 5) & 3;
        int b   = bi >> 7;
#pragma unroll
        for (int i = 0; i < 4; i++) {
            int f = tid + i * 256;
            int r = f >> 4, c = (f & 15) << 2;
            *(float4*)&t[r * 68 + c] =
                *(const float4*)(V + (size_t)(b * SS + kt * 64 + r) * (NKV * DH) + kvh * 64 + c);
        }
        __syncthreads();
        int d = tid >> 2;
        int g = tid & 3;
        int off = g * 16 + (g >> 1) * 4;
        float* out = Vt + ((size_t)(b * NKV + kvh) * DH + d) * VTROW + kt * PR + off;
#pragma unroll
        for (int s4 = 0; s4 < 16; s4 += 4) {
            float vals[4];
#pragma unroll
            for (int q = 0; q < 4; q++) {
                int c   = 4 * (s4 + q) + g;
                int jin = c & 7;
                int pin = (jin < 4) ? (2 * jin) : (2 * (jin - 4) + 1);
                int srow = (c & ~7) | pin;
                vals[q] = t[srow * 68 + d];
            }
            float4 w = make_float4(vals[0], vals[1], vals[2], vals[3]);
            *(float4*)(out + s4) = w;
        }
        return;
    }

    // ---- K rope part (LUT) ----
    int idx = (blockIdx.x - 256) * blockDim.x + tid;
    const int kTotal = MM * NKV * 32;
    if (idx >= kTotal) {
        int i = idx - kTotal;
        if (i < MM) mb[i] = (1.0f - mask[i]) * (-1e9f * LOG2E);
        return;
    }

    int i   = idx & 31;
    int h   = (idx >> 5) % NKV;
    int row = idx / (NKV * 32);
    int s   = row & (SS - 1);
    int b   = row >> 11;

    float cs = lut[s * 64 + i];
    float sn = lut[s * 64 + 32 + i];

    const float* p = kin + (size_t)row * (NKV * 64) + h * 64;
    float x1 = p[i], x2 = p[i + 32];
    float y1 = f2tf(x1 * cs - x2 * sn);
    float y2 = f2tf(x1 * sn + x2 * cs);

    int g = i & 3;
    int off = g * 16 + (g >> 1) * 4;
    float* q = kout + ((size_t)(b * NKV + h) * SS + s) * PR;
    q[off + (i >> 2)]     = y1;
    q[off + (i >> 2) + 8] = y2;
}

// ---------------- flash attention: fused Q-rope, register-resident P ---------
#define BQ 128
#define STG (64 * PR * 2 + 64)                  // K + V + mask per stage
#define ATTN_SMEM ((2 * STG + BQ * PR) * 4)     // ~111 KB
#define QSCALE (0.125f * LOG2E)

__global__ __launch_bounds__(128, 2)
void attn_mma_kernel(const float* __restrict__ Q,    // RAW q projection
                     const float* __restrict__ Kp,   // permuted roped K (tf32)
                     const float* __restrict__ Vt,   // transposed+sigma-permuted V
                     const float* __restrict__ MB,   // mask bias * log2e
                     const float* __restrict__ LUT,  // rope cos/sin
                     float* __restrict__ O)          // ao (tf32-rounded on store)
{
    extern __shared__ float sm[];
    float* P = sm + 2 * STG;   // used only for Q staging

    const int qb = blockIdx.x, h = blockIdx.y, b = blockIdx.z;
    const int kvh = h >> 2;
    const int tid  = threadIdx.x;
    const int lane = tid & 31;
    const int warp = tid >> 5;
    const int gr   = lane >> 2;
    const int tig  = lane & 3;
    const int q0   = warp * 32;
    const int goff = tig * 16 + (tig >> 1) * 4;

    const float* Kbase = Kp + (size_t)(b * NKV + kvh) * SS * PR;
    const float* Vbase = Vt + (size_t)(b * NKV + kvh) * DH * VTROW;

    auto issue = [&](int kt, int bi) {
        float* Ks = sm + bi * STG;
        float* Vs = Ks + 64 * PR;
        float* Ms = Vs + 64 * PR;
#pragma unroll
        for (int i = 0; i < 8; i++) {
            int idx = tid + i * 128;
            int r = idx >> 4, c = idx & 15;
            int g = c >> 2, j = c & 3;
            int fo = g * 16 + (g >> 1) * 4 + 4 * j;
            CPA16(sm_u32(&Ks[r * PR + fo]), Kbase + (size_t)(kt * 64 + r) * PR + fo);
            CPA16(sm_u32(&Vs[r * PR + fo]), Vbase + (size_t)r * VTROW + kt * PR + fo);
        }
        if (tid < 16)
            CPA16(sm_u32(&Ms[tid * 4]), MB + b * SS + kt * 64 + tid * 4);
        CPC();
    };

    issue(0, 0);

    // stage Q tile with fused rope + scale + tf32 (8 pair-chunks per thread)
#pragma unroll
    for (int i = 0; i < 8; i++) {
        int idx = tid + i * 128;
        int r = idx >> 3, pc = (idx & 7) << 2;     // r 0..127, pc 0,4,..,28
        int s = qb * BQ + r;
        const float* qrow = Q + (size_t)(b * SS + s) * DD + h * 64;
        float4 x1 = *(const float4*)(qrow + pc);
        float4 x2 = *(const float4*)(qrow + pc + 32);
        float4 c4 = *(const float4*)(LUT + s * 64 + pc);
        float4 s4 = *(const float4*)(LUT + s * 64 + 32 + pc);
        float4 y1, y2;
        y1.x = f2tf((x1.x * c4.x - x2.x * s4.x) * QSCALE);
        y1.y = f2tf((x1.y * c4.y - x2.y * s4.y) * QSCALE);
        y1.z = f2tf((x1.z * c4.z - x2.z * s4.z) * QSCALE);
        y1.w = f2tf((x1.w * c4.w - x2.w * s4.w) * QSCALE);
        y2.x = f2tf((x1.x * s4.x + x2.x * c4.x) * QSCALE);
        y2.y = f2tf((x1.y * s4.y + x2.y * c4.y) * QSCALE);
        y2.z = f2tf((x1.z * s4.z + x2.z * c4.z) * QSCALE);
        y2.w = f2tf((x1.w * s4.w + x2.w * c4.w) * QSCALE);
        *(float4*)&P[r * PR + pc]      = y1;
        *(float4*)&P[r * PR + pc + 32] = y2;
    }
    __syncthreads();
    unsigned qa[2][8][4];
#pragma unroll
    for (int mt = 0; mt < 2; mt++)
#pragma unroll
        for (int ks = 0; ks < 8; ks++) {
            int r0 = q0 + mt * 16 + gr;
            qa[mt][ks][0] = __float_as_uint(P[r0 * PR + ks * 8 + tig]);
            qa[mt][ks][1] = __float_as_uint(P[(r0 + 8) * PR + ks * 8 + tig]);
            qa[mt][ks][2] = __float_as_uint(P[r0 * PR + ks * 8 + tig + 4]);
            qa[mt][ks][3] = __float_as_uint(P[(r0 + 8) * PR + ks * 8 + tig + 4]);
        }

    float o[2][8][4];
#pragma unroll
    for (int mt = 0; mt < 2; mt++)
#pragma unroll
        for (int nt = 0; nt < 8; nt++)
#pragma unroll
            for (int i = 0; i < 4; i++) o[mt][nt][i] = 0.f;
    float l[4] = {0.f, 0.f, 0.f, 0.f};

    const int NKT = SS / 64;
    for (int kt = 0; kt < NKT; kt++) {
        CPW0();
        __syncthreads();
        if (kt + 1 < NKT) issue(kt + 1, (kt + 1) & 1);

        float* Ks = sm + (kt & 1) * STG;
        float* Vs = Ks + 64 * PR;
        float* Ms = Vs + 64 * PR;

        // prime kr for kb = 0
        float kr[16];
        {
            const float* kbp = Ks + gr * PR + goff;
            *(float4*)(kr)      = *(const float4*)(kbp);
            *(float4*)(kr + 4)  = *(const float4*)(kbp + 4);
            *(float4*)(kr + 8)  = *(const float4*)(kbp + 8);
            *(float4*)(kr + 12) = *(const float4*)(kbp + 12);
        }

#pragma unroll
        for (int kb = 0; kb < 8; kb++) {
            // ---- S fragment for k-block kb ----
            float s0[4] = {0.f, 0.f, 0.f, 0.f};
            float s1[4] = {0.f, 0.f, 0.f, 0.f};
#pragma unroll
            for (int ks = 0; ks < 8; ks++) {
                unsigned bfr[2] = { __float_as_uint(kr[2 * ks]),
                                    __float_as_uint(kr[2 * ks + 1]) };
                mma8(s0, qa[0][ks], bfr, s0);
                mma8(s1, qa[1][ks], bfr, s1);
            }

            // ---- prefetch kr for kb+1 (overlaps softmax + PV below) ----
            float krn[16];
            if (kb < 7) {
                const float* kbn = Ks + ((kb + 1) * 8 + gr) * PR + goff;
                *(float4*)(krn)      = *(const float4*)(kbn);
                *(float4*)(krn + 4)  = *(const float4*)(kbn + 4);
                *(float4*)(krn + 8)  = *(const float4*)(kbn + 8);
                *(float4*)(krn + 12) = *(const float4*)(kbn + 12);
            }

            // ---- softmax -> register-resident A fragments ----
            float2 mbv = *(const float2*)(&Ms[kb * 8 + 2 * tig]);
            float a0f0 = ex2(s0[0] + mbv.x);
            float a0f1 = ex2(s0[2] + mbv.x);
            float a0f2 = ex2(s0[1] + mbv.y);
            float a0f3 = ex2(s0[3] + mbv.y);
            l[0] += a0f0 + a0f2;
            l[1] += a0f1 + a0f3;
            float a1f0 = ex2(s1[0] + mbv.x);
            float a1f1 = ex2(s1[2] + mbv.x);
            float a1f2 = ex2(s1[1] + mbv.y);
            float a1f3 = ex2(s1[3] + mbv.y);
            l[2] += a1f0 + a1f2;
            l[3] += a1f1 + a1f3;

            unsigned a0[4] = { __float_as_uint(a0f0), __float_as_uint(a0f1),
                               __float_as_uint(a0f2), __float_as_uint(a0f3) };
            unsigned a1[4] = { __float_as_uint(a1f0), __float_as_uint(a1f1),
                               __float_as_uint(a1f2), __float_as_uint(a1f3) };

            // ---- O += P(kb) @ V(kb) across all dh tiles ----
#pragma unroll
            for (int ntv = 0; ntv < 8; ntv++) {
                float2 vv = *(const float2*)(&Vs[(ntv * 8 + gr) * PR + goff + 2 * kb]);
                unsigned bfr2[2] = { __float_as_uint(vv.x), __float_as_uint(vv.y) };
                mma8(o[0][ntv], a0, bfr2, o[0][ntv]);
                mma8(o[1][ntv], a1, bfr2, o[1][ntv]);
            }

            if (kb < 7) {
#pragma unroll
                for (int i = 0; i < 16; i++) kr[i] = krn[i];
            }
        }
    }

    // final l reduction
#pragma unroll
    for (int i = 0; i < 4; i++) {
        l[i] += __shfl_xor_sync(0xffffffffu, l[i], 1);
        l[i] += __shfl_xor_sync(0xffffffffu, l[i], 2);
    }

    // normalize + write (tf32-rounded — feeds the pure-copy output GEMM)
#pragma unroll
    for (int mt = 0; mt < 2; mt++) {
        float inv0 = 1.0f / l[mt * 2 + 0], inv1 = 1.0f / l[mt * 2 + 1];
        int rg = b * SS + qb * BQ + q0 + mt * 16 + gr;
#pragma unroll
        for (int nt = 0; nt < 8; nt++) {
            int col = h * 64 + nt * 8 + 2 * tig;
            *(float2*)(&O[(size_t)rg * DD + col]) =
                make_float2(f2tf(o[mt][nt][0] * inv0), f2tf(o[mt][nt][1] * inv0));
            *(float2*)(&O[(size_t)(rg + 8) * DD + col]) =
                make_float2(f2tf(o[mt][nt][2] * inv1), f2tf(o[mt][nt][3] * inv1));
        }
    }
}

// ---------------- launcher ----------------
extern "C" void kernel_launch(void* const* d_in, const int* in_sizes, int n_in,
                              void* d_out, int out_size)
{
    const float* hs   = (const float*)d_in[0];
    const float* mask = (const float*)d_in[1];
    const float* Wq   = (const float*)d_in[2];
    const float* bq   = (const float*)d_in[3];
    const float* Wk   = (const float*)d_in[4];
    const float* bk   = (const float*)d_in[5];
    const float* Wv   = (const float*)d_in[6];
    const float* bv   = (const float*)d_in[7];
    const float* Wo   = (const float*)d_in[8];
    const float* bo   = (const float*)d_in[9];
    float* out = (float*)d_out;

    float *q, *k, *v, *kr, *vt, *ao, *mb, *lut;
    float *hsr, *wq, *wk, *wv, *wo;
    cudaGetSymbolAddress((void**)&q,   g_q);
    cudaGetSymbolAddress((void**)&k,   g_k);
    cudaGetSymbolAddress((void**)&v,   g_v);
    cudaGetSymbolAddress((void**)&kr,  g_kr);
    cudaGetSymbolAddress((void**)&vt,  g_vt);
    cudaGetSymbolAddress((void**)&ao,  g_ao);
    cudaGetSymbolAddress((void**)&mb,  g_mb);
    cudaGetSymbolAddress((void**)&lut, g_lut);
    cudaGetSymbolAddress((void**)&hsr, g_hsr);
    cudaGetSymbolAddress((void**)&wq,  g_wq);
    cudaGetSymbolAddress((void**)&wk,  g_wk);
    cudaGetSymbolAddress((void**)&wv,  g_wv);
    cudaGetSymbolAddress((void**)&wo,  g_wo);

    cudaFuncSetAttribute(proj_all, cudaFuncAttributeMaxDynamicSharedMemorySize, GSMEM);
    cudaFuncSetAttribute(tgemm_o,  cudaFuncAttributeMaxDynamicSharedMemorySize, GSMEM);
    cudaFuncSetAttribute(attn_mma_kernel, cudaFuncAttributeMaxDynamicSharedMemorySize, ATTN_SMEM);

    // tf32-round inputs + build rope LUT (1703936 float4 + 65536 LUT tasks)
    prep_kernel<<<6912, 256>>>((const float4*)hs, (const float4*)Wq, (const float4*)Wk,
                               (const float4*)Wv, (const float4*)Wo,
                               (float4*)hsr, (float4*)wq, (float4*)wk,
                               (float4*)wv, (float4*)wo, lut);

    // Q/K/V projections in one launch (pure-copy cp.async tiles)
    proj_all<<<dim3(12, MM / TBM), 256, GSMEM>>>(hsr, wq, bq, wk, bk, wv, bv, q, k, v);

    // K rope (LUT) + vtrans (sigma) + mask bias in one launch
    {
        int ropeBlocks = (MM * NKV * 32 + MM + 255) / 256;
        post_kernel<<<256 + ropeBlocks, 256>>>(k, kr, v, vt, mask, mb, lut);
    }

    // attention (Q rope fused into staging)
    attn_mma_kernel<<<dim3(SS / BQ, NH, BB), 128, ATTN_SMEM>>>(q, kr, vt, mb, lut, ao);

    // output projection
    tgemm_o<<<dim3(DD / TBN, MM / TBM), 256, GSMEM>>>(ao, wo, bo, out);
}